// round 16
// baseline (speedup 1.0000x reference)
#include <cuda_runtime.h>
#include <cuda_fp16.h>
#include <cstdint>

// ---------------- problem constants ----------------
#define NB    16
#define NCIN  128
#define NCOUT 128
#define NHW   128
#define NPIX  16384
#define NK    64
#define KCOLS 294912
#define NTILE 4096          // 64x64 Winograd output tiles per (b, plane)
#define ARPAD 136           // halfs per A smem row (128 + 8 pad; 272B stride, conflict-free)
#define BRPAD 72            // halfs per B smem row (64 tiles + 8 pad; 144B stride)
#define ASTG  (128 * ARPAD) // halfs per A stage (17408) -- 128 oc x 128 ic
#define BSTG  (128 * BRPAD) // halfs per B stage (9216)  -- 128 ic x 64 tiles
#define NSTG  16            // pipeline stages: one per m-component
#define NBUF  4             // smem ring depth (prefetch distance 2)

// ---------------- scratch ----------------
__device__ float  g_pooled[NB * NCIN];
__device__ float  g_att[NB * NK];
__device__ float  g_agg[(size_t)NB * KCOLS];                    // 18.9 MB
__device__ __half g_U[(size_t)NB * 16 * NCOUT * NCIN];          // 8.4 MB  [b][m][oc][ic]
__device__ __half g_V[(size_t)NB * 16 * NCIN * NTILE];          // 268 MB  [b][m][ic][tile]

// ---------------- helpers ----------------
__device__ __forceinline__ uint32_t smem_u32(const void* p) {
    uint32_t a;
    asm("{ .reg .u64 t; cvta.to.shared.u64 t, %1; cvt.u32.u64 %0, t; }" : "=r"(a) : "l"(p));
    return a;
}
#define CP_A16(dst, src) \
    asm volatile("cp.async.ca.shared.global [%0], [%1], 16;" :: "r"(dst), "l"(src) : "memory")
#define CP_COMMIT() asm volatile("cp.async.commit_group;" ::: "memory")
#define CP_WAIT0()  asm volatile("cp.async.wait_group 0;" ::: "memory")
#define CP_WAIT2()  asm volatile("cp.async.wait_group 2;" ::: "memory")

#define LDM(q, addr) \
    asm volatile("ldmatrix.sync.aligned.m8n8.x4.shared.b16 {%0,%1,%2,%3}, [%4];" \
        : "=r"((q)[0]), "=r"((q)[1]), "=r"((q)[2]), "=r"((q)[3]) : "r"(addr))
#define LDMT(q, addr) \
    asm volatile("ldmatrix.sync.aligned.m8n8.x4.trans.shared.b16 {%0,%1,%2,%3}, [%4];" \
        : "=r"((q)[0]), "=r"((q)[1]), "=r"((q)[2]), "=r"((q)[3]) : "r"(addr))

#define MMAH(C, qa, b0, b1) \
    asm volatile("mma.sync.aligned.m16n8k16.row.col.f32.f16.f16.f32 " \
        "{%0,%1,%2,%3},{%4,%5,%6,%7},{%8,%9},{%0,%1,%2,%3};" \
        : "+f"((C)[0]), "+f"((C)[1]), "+f"((C)[2]), "+f"((C)[3]) \
        : "r"((qa)[0]), "r"((qa)[1]), "r"((qa)[2]), "r"((qa)[3]), "r"(b0), "r"(b1))

// ---------------- 1) input transform + fused global pool --------------------
__global__ void __launch_bounds__(256) wino_input_kernel(const float* __restrict__ x) {
    int blk = blockIdx.x;
    int b = blk >> 7;
    int ic = blk & 127;
    int tid = threadIdx.x;
    int tx2 = tid & 31;
    int tyb = tid >> 5;

    const float* xp = x + ((size_t)(b * 128 + ic)) * NPIX;
    __half* vb = g_V + ((size_t)(b * 16) * 128 + ic) * NTILE;

    float psum = 0.f;

    #pragma unroll 1
    for (int j = 0; j < 8; j++) {
        int ty = j * 8 + tyb;
        int tile = ty * 64 + 2 * tx2;
        int y0 = 2 * ty - 1;
        int x0 = 4 * tx2 - 1;
        float d[4][6];
        #pragma unroll
        for (int r = 0; r < 4; r++) {
            int yy = y0 + r;
            bool yok = (unsigned)yy < 128u;
            #pragma unroll
            for (int c = 0; c < 6; c++) {
                int xx = x0 + c;
                d[r][c] = (yok && (unsigned)xx < 128u) ? xp[yy * 128 + xx] : 0.f;
            }
        }
        psum += d[1][1] + d[1][2] + d[1][3] + d[1][4]
              + d[2][1] + d[2][2] + d[2][3] + d[2][4];

        float w0[4][4], w1[4][4];
        #pragma unroll
        for (int c = 0; c < 4; c++) {
            w0[0][c] = d[0][c] - d[2][c];
            w0[1][c] = d[1][c] + d[2][c];
            w0[2][c] = d[2][c] - d[1][c];
            w0[3][c] = d[1][c] - d[3][c];
            w1[0][c] = d[0][c + 2] - d[2][c + 2];
            w1[1][c] = d[1][c + 2] + d[2][c + 2];
            w1[2][c] = d[2][c + 2] - d[1][c + 2];
            w1[3][c] = d[1][c + 2] - d[3][c + 2];
        }
        #pragma unroll
        for (int r = 0; r < 4; r++) {
            float a0 = w0[r][0] - w0[r][2];
            float a1 = w0[r][1] + w0[r][2];
            float a2 = w0[r][2] - w0[r][1];
            float a3 = w0[r][1] - w0[r][3];
            float b0 = w1[r][0] - w1[r][2];
            float b1 = w1[r][1] + w1[r][2];
            float b2 = w1[r][2] - w1[r][1];
            float b3 = w1[r][1] - w1[r][3];
            *(__half2*)(vb + (size_t)(r * 4 + 0) * (128 * NTILE) + tile) = __floats2half2_rn(a0, b0);
            *(__half2*)(vb + (size_t)(r * 4 + 1) * (128 * NTILE) + tile) = __floats2half2_rn(a1, b1);
            *(__half2*)(vb + (size_t)(r * 4 + 2) * (128 * NTILE) + tile) = __floats2half2_rn(a2, b2);
            *(__half2*)(vb + (size_t)(r * 4 + 3) * (128 * NTILE) + tile) = __floats2half2_rn(a3, b3);
        }
    }

    __shared__ float sd[256];
    sd[tid] = psum;
    __syncthreads();
    for (int off = 128; off > 0; off >>= 1) {
        if (tid < off) sd[tid] += sd[tid + off];
        __syncthreads();
    }
    if (tid == 0) g_pooled[b * 128 + ic] = sd[0] * (1.f / (float)NPIX);
}

// ---------------- 2) attention ----------------
__global__ void att_kernel(const float* __restrict__ ksm_w) {
    int tid = threadIdx.x;
    int b = tid >> 6;
    int k = tid & 63;
    float s = 0.f;
    #pragma unroll 8
    for (int c = 0; c < NCIN; c++)
        s += g_pooled[b * NCIN + c] * ksm_w[k * NCIN + c];
    float sig = 1.f / (1.f + expf(-s));
    __shared__ float sl[1024];
    sl[tid] = sig;
    __syncthreads();
    float mx = -1e30f;
    #pragma unroll 8
    for (int i = 0; i < NK; i++) mx = fmaxf(mx, sl[b * NK + i]);
    float sum = 0.f;
    #pragma unroll 8
    for (int i = 0; i < NK; i++) sum += expf(sl[b * NK + i] - mx);
    g_att[tid] = expf(sig - mx) / sum;
}

// ---------------- 3) aggregate over kernel bank ----------------
__global__ void __launch_bounds__(256) agg_kernel(const float* __restrict__ dft) {
    __shared__ float s_att[NB * NK];
    int tid = threadIdx.x;
    #pragma unroll
    for (int i = 0; i < 4; i++) s_att[tid + i * 256] = g_att[tid + i * 256];
    __syncthreads();

    int base = blockIdx.x * 1024 + tid;
    float acc[16][4];
    #pragma unroll
    for (int b = 0; b < 16; b++)
        #pragma unroll
        for (int c = 0; c < 4; c++) acc[b][c] = 0.f;

    for (int k = 0; k < NK; k++) {
        const float* row = dft + (size_t)k * KCOLS + base;
        float w0 = row[0], w1 = row[256], w2 = row[512], w3 = row[768];
        #pragma unroll
        for (int b = 0; b < 16; b++) {
            float a = s_att[b * NK + k];
            acc[b][0] = fmaf(a, w0, acc[b][0]);
            acc[b][1] = fmaf(a, w1, acc[b][1]);
            acc[b][2] = fmaf(a, w2, acc[b][2]);
            acc[b][3] = fmaf(a, w3, acc[b][3]);
        }
    }
    #pragma unroll
    for (int b = 0; b < 16; b++)
        #pragma unroll
        for (int c = 0; c < 4; c++)
            g_agg[(size_t)b * KCOLS + base + c * 256] = acc[b][c];
}

// ---------------- 4) weight: iFFT + clip + Winograd U = G g G^T ----------------
__global__ void wino_weight_kernel() {
    int id = blockIdx.x * 256 + threadIdx.x;
    int ic = id & 127;
    int oc = (id >> 7) & 127;
    int b = id >> 14;

    const float* a = g_agg + (size_t)b * KCOLS + (size_t)(oc * 128 + ic) * 18;
    float re[9], im[9];
    #pragma unroll
    for (int t = 0; t < 9; t++) { re[t] = a[2 * t]; im[t] = a[2 * t + 1]; }

    const float C3[3] = {1.f, -0.5f, -0.5f};
    const float S3[3] = {0.f, 0.86602540378443864676f, -0.86602540378443864676f};
    float gk[3][3];
    #pragma unroll
    for (int p = 0; p < 3; p++)
        #pragma unroll
        for (int q = 0; q < 3; q++) {
            float s = 0.f;
            #pragma unroll
            for (int u = 0; u < 3; u++)
                #pragma unroll
                for (int v = 0; v < 3; v++) {
                    int m = (u * p + v * q) % 3;
                    s += re[u * 3 + v] * C3[m] - im[u * 3 + v] * S3[m];
                }
            s *= (1.f / 3.f);
            gk[p][q] = fminf(10.f, fmaxf(-10.f, s));
        }

    float w[4][3];
    #pragma unroll
    for (int j = 0; j < 3; j++) {
        w[0][j] = gk[0][j];
        w[1][j] = 0.5f * (gk[0][j] + gk[1][j] + gk[2][j]);
        w[2][j] = 0.5f * (gk[0][j] - gk[1][j] + gk[2][j]);
        w[3][j] = gk[2][j];
    }
    __half* ub = g_U + ((size_t)b * 16) * 16384 + oc * 128 + ic;
    #pragma unroll
    for (int i = 0; i < 4; i++) {
        float u0 = w[i][0];
        float u1 = 0.5f * (w[i][0] + w[i][1] + w[i][2]);
        float u2 = 0.5f * (w[i][0] - w[i][1] + w[i][2]);
        float u3 = w[i][2];
        ub[(size_t)(i * 4 + 0) * 16384] = __float2half_rn(u0);
        ub[(size_t)(i * 4 + 1) * 16384] = __float2half_rn(u1);
        ub[(size_t)(i * 4 + 2) * 16384] = __float2half_rn(u2);
        ub[(size_t)(i * 4 + 3) * 16384] = __float2half_rn(u3);
    }
}

// ---------------- 5) fused GEMM (16 m-components) + output transform --------
// CTA = (tile-row of 64, b). M=128 oc, N=64 tiles, K-stage = 128 ic (full),
// 16 stages (one per m), 4-buffer cp.async ring, prefetch distance 2,
// wait_group 2, one barrier per stage. 8 warps: (wid&3)->oc grp 32,
// (wid>>2)->tile grp 32. 64 MMAs/warp/stage. 1 CTA/SM.
__global__ void __launch_bounds__(256, 1) wino_gemm_kernel(
    const float* __restrict__ bias,
    const float* __restrict__ fbm,
    float* __restrict__ out) {

    extern __shared__ __half sh[];
    __half* const As = sh;                 // NBUF * ASTG
    __half* const Bs = sh + NBUF * ASTG;   // NBUF * BSTG

    const int tid = threadIdx.x;
    const int lane = tid & 31;
    const int wid = tid >> 5;
    const int g = lane >> 2;
    const int tig = lane & 3;
    const int mb = (wid & 3) * 32;
    const int nw = wid >> 2;             // 0,1 -> tile group of 32
    const int t0 = blockIdx.x * 64;      // one full tile-row
    const int b = blockIdx.y;

    const __half* Ub = g_U + (size_t)b * 16 * 16384;          // [m][oc][ic]
    const __half* Vb = g_V + (size_t)b * 16 * 128 * NTILE;    // [m][ic][tile]

    const uint32_t as_u = smem_u32(As);
    const uint32_t bs_u = smem_u32(Bs);
    // A cp.async: 2048 16B chunks per stage; thread covers 8
    const uint32_t a_dst0 = as_u + (uint32_t)((tid >> 4) * ARPAD + (tid & 15) * 8) * 2;
    // B cp.async: 1024 chunks; thread covers 4
    const uint32_t b_dst0 = bs_u + (uint32_t)((tid >> 3) * BRPAD + (tid & 7) * 8) * 2;

    // ldmatrix addressing
    const int a_row = (lane & 7) + (((lane >> 3) & 1) << 3);
    const int a_k8 = (lane >> 4) * 8;
    const uint32_t a_base = as_u + (uint32_t)((mb + a_row) * ARPAD + a_k8) * 2;
    const uint32_t b_base = bs_u + (uint32_t)((lane & 15) * BRPAD + nw * 32 + (lane >> 4) * 8) * 2;

    float o[2][4][2][2][4];   // [mt][nt][r][p][x]  = 128 regs
    #pragma unroll
    for (int i = 0; i < 2; i++)
        #pragma unroll
        for (int j = 0; j < 4; j++)
            #pragma unroll
            for (int r = 0; r < 2; r++)
                #pragma unroll
                for (int p = 0; p < 2; p++)
                    #pragma unroll
                    for (int xq = 0; xq < 4; xq++) o[i][j][r][p][xq] = 0.f;

    float acc[2][4][4];
    #pragma unroll
    for (int i = 0; i < 2; i++)
        #pragma unroll
        for (int j = 0; j < 4; j++)
            #pragma unroll
            for (int q = 0; q < 4; q++) acc[i][j][q] = 0.f;

    // stage s == m-component s; buffer = s & 3
    #define LOADST(s)                                                                 \
    {                                                                                 \
        const __half* ua = Ub + (size_t)(s) * 16384                                   \
                           + (tid >> 4) * 128 + (tid & 15) * 8;                       \
        uint32_t aoff = (uint32_t)((s) & 3) * (ASTG * 2);                             \
        _Pragma("unroll")                                                             \
        for (int i = 0; i < 8; i++)                                                   \
            CP_A16(a_dst0 + aoff + i * (16 * ARPAD * 2), ua + i * (16 * 128));        \
        const __half* sb = Vb + ((size_t)(s) * 128 + (tid >> 3)) * NTILE              \
                           + t0 + (tid & 7) * 8;                                      \
        uint32_t boff = (uint32_t)((s) & 3) * (BSTG * 2);                             \
        _Pragma("unroll")                                                             \
        for (int i = 0; i < 4; i++)                                                   \
            CP_A16(b_dst0 + boff + i * (32 * BRPAD * 2), sb + (size_t)(i * 32) * NTILE); \
    }

    #define COMPUTE(s)                                                                \
    {                                                                                 \
        uint32_t ao = (uint32_t)((s) & 3) * (ASTG * 2);                               \
        uint32_t bo = (uint32_t)((s) & 3) * (BSTG * 2);                               \
        _Pragma("unroll")                                                             \
        for (int kc = 0; kc < 8; kc++) {                                              \
            uint32_t qa0[4], qa1[4], qb0[4], qb1[4];                                  \
            LDM(qa0, a_base + ao + kc * 32);                                          \
            LDM(qa1, a_base + ao + kc * 32 + 16 * ARPAD * 2);                         \
            LDMT(qb0, b_base + bo + kc * (16 * BRPAD * 2));                           \
            LDMT(qb1, b_base + bo + kc * (16 * BRPAD * 2) + 32);                      \
            MMAH(acc[0][0], qa0, qb0[0], qb0[1]);                                     \
            MMAH(acc[1][0], qa1, qb0[0], qb0[1]);                                     \
            MMAH(acc[0][1], qa0, qb0[2], qb0[3]);                                     \
            MMAH(acc[1][1], qa1, qb0[2], qb0[3]);                                     \
            MMAH(acc[0][2], qa0, qb1[0], qb1[1]);                                     \
            MMAH(acc[1][2], qa1, qb1[0], qb1[1]);                                     \
            MMAH(acc[0][3], qa0, qb1[2], qb1[3]);                                     \
            MMAH(acc[1][3], qa1, qb1[2], qb1[3]);                                     \
        }                                                                             \
    }

    // prologue: stages 0 and 1 in flight (distance 2)
    LOADST(0);
    CP_COMMIT();
    LOADST(1);
    CP_COMMIT();

    const float CA0[4] = {1.f, 1.f, 1.f, 0.f};
    const float CA1[4] = {0.f, 1.f, -1.f, -1.f};

    #pragma unroll 1
    for (int m = 0; m < 16; m++) {
        if (m < NSTG - 2) {
            LOADST(m + 2);
            CP_COMMIT();
            CP_WAIT2();          // group m done; m+1, m+2 in flight
        } else {
            CP_WAIT0();          // drain (tail stages)
        }
        __syncthreads();         // stage-m A + B visible to all; overwrite-safe
        COMPUTE(m);

        // fold component m into output registers
        int u = m >> 2, v = m & 3;
        float cy0 = CA0[u], cy1 = CA1[u];
        float cx0 = CA0[v], cx1 = CA1[v];
        float c00 = cy0 * cx0, c01 = cy0 * cx1, c10 = cy1 * cx0, c11 = cy1 * cx1;
        #pragma unroll
        for (int mt = 0; mt < 2; mt++)
            #pragma unroll
            for (int nt = 0; nt < 4; nt++)
                #pragma unroll
                for (int i = 0; i < 4; i++) {
                    float a = acc[mt][nt][i];
                    int r = i >> 1, tl = i & 1;
                    o[mt][nt][r][0][2 * tl + 0] = fmaf(c00, a, o[mt][nt][r][0][2 * tl + 0]);
                    o[mt][nt][r][0][2 * tl + 1] = fmaf(c01, a, o[mt][nt][r][0][2 * tl + 1]);
                    o[mt][nt][r][1][2 * tl + 0] = fmaf(c10, a, o[mt][nt][r][1][2 * tl + 0]);
                    o[mt][nt][r][1][2 * tl + 1] = fmaf(c11, a, o[mt][nt][r][1][2 * tl + 1]);
                    acc[mt][nt][i] = 0.f;
                }
    }

    // epilogue: (o + bias) * fbm -> out  (tile-row, fully coalesced float4)
    int ty = blockIdx.x;
    #pragma unroll
    for (int mt = 0; mt < 2; mt++)
        #pragma unroll
        for (int r = 0; r < 2; r++) {
            int oc = mb + mt * 16 + g + r * 8;
            float bi = bias[oc];
            float sc = fbm[oc];
            #pragma unroll
            for (int nt = 0; nt < 4; nt++) {
                int xg = 64 * nw + 16 * nt + 4 * tig;
                #pragma unroll
                for (int p = 0; p < 2; p++) {
                    int yg = 2 * ty + p;
                    float4 vv;
                    vv.x = (o[mt][nt][r][p][0] + bi) * sc;
                    vv.y = (o[mt][nt][r][p][1] + bi) * sc;
                    vv.z = (o[mt][nt][r][p][2] + bi) * sc;
                    vv.w = (o[mt][nt][r][p][3] + bi) * sc;
                    *(float4*)(out + (((size_t)(b * NCOUT + oc)) * NHW + yg) * NHW + xg) = vv;
                }
            }
        }
}

// ---------------- launch ----------------
extern "C" void kernel_launch(void* const* d_in, const int* in_sizes, int n_in,
                              void* d_out, int out_size) {
    const float* x    = (const float*)d_in[0];
    const float* dft  = (const float*)d_in[1];
    const float* ksm  = (const float*)d_in[2];
    const float* bias = (const float*)d_in[3];
    const float* fbm  = (const float*)d_in[4];
    float* out = (float*)d_out;

    wino_input_kernel<<<NB * NCIN, 256>>>(x);          // also produces g_pooled
    att_kernel<<<1, 1024>>>(ksm);
    agg_kernel<<<KCOLS / 1024, 256>>>(dft);
    wino_weight_kernel<<<(NB * NCOUT * NCIN) / 256, 256>>>();

    const int dyn = NBUF * (ASTG + BSTG) * 2;          // 212,992 bytes
    cudaFuncSetAttribute(wino_gemm_kernel, cudaFuncAttributeMaxDynamicSharedMemorySize, dyn);
    wino_gemm_kernel<<<dim3(NTILE / 64, NB), 256, dyn>>>(bias, fbm, out);
}

// round 17
// speedup vs baseline: 1.0788x; 1.0788x over previous
#include <cuda_runtime.h>
#include <cuda_fp16.h>
#include <cstdint>

// ---------------- problem constants ----------------
#define NB    16
#define NCIN  128
#define NCOUT 128
#define NHW   128
#define NPIX  16384
#define NK    64
#define KCOLS 294912
#define NTILE 4096          // 64x64 Winograd output tiles per (b, plane)
#define ARPAD 136           // halfs per A smem row (128 + 8 pad; 272B stride, conflict-free)
#define BRPAD 72            // halfs per B smem row (64 tiles + 8 pad; 144B stride)
#define ASTG  (128 * ARPAD) // halfs per A stage (17408) -- 128 oc x 128 ic
#define BSTG  (128 * BRPAD) // halfs per B stage (9216)  -- 128 ic x 64 tiles
#define NSTG  16            // pipeline stages: one per m-component

// ---------------- scratch ----------------
__device__ float  g_pooled[NB * NCIN];
__device__ float  g_att[NB * NK];
__device__ __half g_agg[(size_t)NB * KCOLS];                    // 9.4 MB (fp16 intermediate)
__device__ __half g_U[(size_t)NB * 16 * NCOUT * NCIN];          // 8.4 MB  [b][m][oc][ic]
__device__ __half g_V[(size_t)NB * 16 * NCIN * NTILE];          // 268 MB  [b][m][ic][tile]

// ---------------- helpers ----------------
__device__ __forceinline__ uint32_t smem_u32(const void* p) {
    uint32_t a;
    asm("{ .reg .u64 t; cvta.to.shared.u64 t, %1; cvt.u32.u64 %0, t; }" : "=r"(a) : "l"(p));
    return a;
}
#define CP_A16(dst, src) \
    asm volatile("cp.async.ca.shared.global [%0], [%1], 16;" :: "r"(dst), "l"(src) : "memory")
#define CP_COMMIT() asm volatile("cp.async.commit_group;" ::: "memory")
#define CP_WAIT0()  asm volatile("cp.async.wait_group 0;" ::: "memory")
#define CP_WAIT1()  asm volatile("cp.async.wait_group 1;" ::: "memory")

#define LDM(q, addr) \
    asm volatile("ldmatrix.sync.aligned.m8n8.x4.shared.b16 {%0,%1,%2,%3}, [%4];" \
        : "=r"((q)[0]), "=r"((q)[1]), "=r"((q)[2]), "=r"((q)[3]) : "r"(addr))
#define LDMT(q, addr) \
    asm volatile("ldmatrix.sync.aligned.m8n8.x4.trans.shared.b16 {%0,%1,%2,%3}, [%4];" \
        : "=r"((q)[0]), "=r"((q)[1]), "=r"((q)[2]), "=r"((q)[3]) : "r"(addr))

#define MMAH(C, qa, b0, b1) \
    asm volatile("mma.sync.aligned.m16n8k16.row.col.f32.f16.f16.f32 " \
        "{%0,%1,%2,%3},{%4,%5,%6,%7},{%8,%9},{%0,%1,%2,%3};" \
        : "+f"((C)[0]), "+f"((C)[1]), "+f"((C)[2]), "+f"((C)[3]) \
        : "r"((qa)[0]), "r"((qa)[1]), "r"((qa)[2]), "r"((qa)[3]), "r"(b0), "r"(b1))

// ---------------- 1) input transform + fused global pool --------------------
__global__ void __launch_bounds__(256) wino_input_kernel(const float* __restrict__ x) {
    int blk = blockIdx.x;
    int b = blk >> 7;
    int ic = blk & 127;
    int tid = threadIdx.x;
    int tx2 = tid & 31;
    int tyb = tid >> 5;

    const float* xp = x + ((size_t)(b * 128 + ic)) * NPIX;
    __half* vb = g_V + ((size_t)(b * 16) * 128 + ic) * NTILE;

    float psum = 0.f;

    #pragma unroll 1
    for (int j = 0; j < 8; j++) {
        int ty = j * 8 + tyb;
        int tile = ty * 64 + 2 * tx2;
        int y0 = 2 * ty - 1;
        int x0 = 4 * tx2 - 1;
        float d[4][6];
        #pragma unroll
        for (int r = 0; r < 4; r++) {
            int yy = y0 + r;
            bool yok = (unsigned)yy < 128u;
            #pragma unroll
            for (int c = 0; c < 6; c++) {
                int xx = x0 + c;
                d[r][c] = (yok && (unsigned)xx < 128u) ? xp[yy * 128 + xx] : 0.f;
            }
        }
        psum += d[1][1] + d[1][2] + d[1][3] + d[1][4]
              + d[2][1] + d[2][2] + d[2][3] + d[2][4];

        float w0[4][4], w1[4][4];
        #pragma unroll
        for (int c = 0; c < 4; c++) {
            w0[0][c] = d[0][c] - d[2][c];
            w0[1][c] = d[1][c] + d[2][c];
            w0[2][c] = d[2][c] - d[1][c];
            w0[3][c] = d[1][c] - d[3][c];
            w1[0][c] = d[0][c + 2] - d[2][c + 2];
            w1[1][c] = d[1][c + 2] + d[2][c + 2];
            w1[2][c] = d[2][c + 2] - d[1][c + 2];
            w1[3][c] = d[1][c + 2] - d[3][c + 2];
        }
        #pragma unroll
        for (int r = 0; r < 4; r++) {
            float a0 = w0[r][0] - w0[r][2];
            float a1 = w0[r][1] + w0[r][2];
            float a2 = w0[r][2] - w0[r][1];
            float a3 = w0[r][1] - w0[r][3];
            float b0 = w1[r][0] - w1[r][2];
            float b1 = w1[r][1] + w1[r][2];
            float b2 = w1[r][2] - w1[r][1];
            float b3 = w1[r][1] - w1[r][3];
            *(__half2*)(vb + (size_t)(r * 4 + 0) * (128 * NTILE) + tile) = __floats2half2_rn(a0, b0);
            *(__half2*)(vb + (size_t)(r * 4 + 1) * (128 * NTILE) + tile) = __floats2half2_rn(a1, b1);
            *(__half2*)(vb + (size_t)(r * 4 + 2) * (128 * NTILE) + tile) = __floats2half2_rn(a2, b2);
            *(__half2*)(vb + (size_t)(r * 4 + 3) * (128 * NTILE) + tile) = __floats2half2_rn(a3, b3);
        }
    }

    __shared__ float sd[256];
    sd[tid] = psum;
    __syncthreads();
    for (int off = 128; off > 0; off >>= 1) {
        if (tid < off) sd[tid] += sd[tid + off];
        __syncthreads();
    }
    if (tid == 0) g_pooled[b * 128 + ic] = sd[0] * (1.f / (float)NPIX);
}

// ---------------- 2) attention ----------------
__global__ void att_kernel(const float* __restrict__ ksm_w) {
    int tid = threadIdx.x;
    int b = tid >> 6;
    int k = tid & 63;
    float s = 0.f;
    #pragma unroll 8
    for (int c = 0; c < NCIN; c++)
        s += g_pooled[b * NCIN + c] * ksm_w[k * NCIN + c];
    float sig = 1.f / (1.f + expf(-s));
    __shared__ float sl[1024];
    sl[tid] = sig;
    __syncthreads();
    float mx = -1e30f;
    #pragma unroll 8
    for (int i = 0; i < NK; i++) mx = fmaxf(mx, sl[b * NK + i]);
    float sum = 0.f;
    #pragma unroll 8
    for (int i = 0; i < NK; i++) sum += expf(sl[b * NK + i] - mx);
    g_att[tid] = expf(sig - mx) / sum;
}

// ---------------- 3) aggregate over kernel bank (fp16 output) ----------------
__global__ void __launch_bounds__(256) agg_kernel(const float* __restrict__ dft) {
    __shared__ float s_att[NB * NK];
    int tid = threadIdx.x;
    #pragma unroll
    for (int i = 0; i < 4; i++) s_att[tid + i * 256] = g_att[tid + i * 256];
    __syncthreads();

    int base = blockIdx.x * 1024 + tid;
    float acc[16][4];
    #pragma unroll
    for (int b = 0; b < 16; b++)
        #pragma unroll
        for (int c = 0; c < 4; c++) acc[b][c] = 0.f;

    for (int k = 0; k < NK; k++) {
        const float* row = dft + (size_t)k * KCOLS + base;
        float w0 = row[0], w1 = row[256], w2 = row[512], w3 = row[768];
        #pragma unroll
        for (int b = 0; b < 16; b++) {
            float a = s_att[b * NK + k];
            acc[b][0] = fmaf(a, w0, acc[b][0]);
            acc[b][1] = fmaf(a, w1, acc[b][1]);
            acc[b][2] = fmaf(a, w2, acc[b][2]);
            acc[b][3] = fmaf(a, w3, acc[b][3]);
        }
    }
    #pragma unroll
    for (int b = 0; b < 16; b++)
        #pragma unroll
        for (int c = 0; c < 4; c++)
            g_agg[(size_t)b * KCOLS + base + c * 256] = __float2half_rn(acc[b][c]);
}

// ---------------- 4) weight: iFFT + clip + Winograd U = G g G^T ----------------
__global__ void wino_weight_kernel() {
    int id = blockIdx.x * 256 + threadIdx.x;
    int ic = id & 127;
    int oc = (id >> 7) & 127;
    int b = id >> 14;

    const __half* a = g_agg + (size_t)b * KCOLS + (size_t)(oc * 128 + ic) * 18;
    float re[9], im[9];
    #pragma unroll
    for (int t = 0; t < 9; t++) {
        re[t] = __half2float(a[2 * t]);
        im[t] = __half2float(a[2 * t + 1]);
    }

    const float C3[3] = {1.f, -0.5f, -0.5f};
    const float S3[3] = {0.f, 0.86602540378443864676f, -0.86602540378443864676f};
    float gk[3][3];
    #pragma unroll
    for (int p = 0; p < 3; p++)
        #pragma unroll
        for (int q = 0; q < 3; q++) {
            float s = 0.f;
            #pragma unroll
            for (int u = 0; u < 3; u++)
                #pragma unroll
                for (int v = 0; v < 3; v++) {
                    int m = (u * p + v * q) % 3;
                    s += re[u * 3 + v] * C3[m] - im[u * 3 + v] * S3[m];
                }
            s *= (1.f / 3.f);
            gk[p][q] = fminf(10.f, fmaxf(-10.f, s));
        }

    float w[4][3];
    #pragma unroll
    for (int j = 0; j < 3; j++) {
        w[0][j] = gk[0][j];
        w[1][j] = 0.5f * (gk[0][j] + gk[1][j] + gk[2][j]);
        w[2][j] = 0.5f * (gk[0][j] - gk[1][j] + gk[2][j]);
        w[3][j] = gk[2][j];
    }
    __half* ub = g_U + ((size_t)b * 16) * 16384 + oc * 128 + ic;
    #pragma unroll
    for (int i = 0; i < 4; i++) {
        float u0 = w[i][0];
        float u1 = 0.5f * (w[i][0] + w[i][1] + w[i][2]);
        float u2 = 0.5f * (w[i][0] - w[i][1] + w[i][2]);
        float u3 = w[i][2];
        ub[(size_t)(i * 4 + 0) * 16384] = __float2half_rn(u0);
        ub[(size_t)(i * 4 + 1) * 16384] = __float2half_rn(u1);
        ub[(size_t)(i * 4 + 2) * 16384] = __float2half_rn(u2);
        ub[(size_t)(i * 4 + 3) * 16384] = __float2half_rn(u3);
    }
}

// ---------------- 5) fused GEMM (16 m-components) + output transform --------
// CTA = (tile-row of 64, b). M=128 oc, N=64 tiles, K-stage = 128 ic (full),
// 16 stages (one per m), 3-buffer cp.async ring, wait_group 1, one barrier
// per stage. 8 warps: (wid&3)->oc grp 32, (wid>>2)->tile grp 32.
// 64 MMAs/warp/stage. 1 CTA/SM. (R14 configuration — measured optimum.)
__global__ void __launch_bounds__(256, 1) wino_gemm_kernel(
    const float* __restrict__ bias,
    const float* __restrict__ fbm,
    float* __restrict__ out) {

    extern __shared__ __half sh[];
    __half* const As = sh;              // 3 * ASTG
    __half* const Bs = sh + 3 * ASTG;   // 3 * BSTG

    const int tid = threadIdx.x;
    const int lane = tid & 31;
    const int wid = tid >> 5;
    const int g = lane >> 2;
    const int tig = lane & 3;
    const int mb = (wid & 3) * 32;
    const int nw = wid >> 2;             // 0,1 -> tile group of 32
    const int t0 = blockIdx.x * 64;      // one full tile-row
    const int b = blockIdx.y;

    const __half* Ub = g_U + (size_t)b * 16 * 16384;          // [m][oc][ic]
    const __half* Vb = g_V + (size_t)b * 16 * 128 * NTILE;    // [m][ic][tile]

    const uint32_t as_u = smem_u32(As);
    const uint32_t bs_u = smem_u32(Bs);
    // A cp.async: 2048 16B chunks per stage; thread covers 8
    const uint32_t a_dst0 = as_u + (uint32_t)((tid >> 4) * ARPAD + (tid & 15) * 8) * 2;
    // B cp.async: 1024 chunks; thread covers 4
    const uint32_t b_dst0 = bs_u + (uint32_t)((tid >> 3) * BRPAD + (tid & 7) * 8) * 2;

    // ldmatrix addressing
    const int a_row = (lane & 7) + (((lane >> 3) & 1) << 3);
    const int a_k8 = (lane >> 4) * 8;
    const uint32_t a_base = as_u + (uint32_t)((mb + a_row) * ARPAD + a_k8) * 2;
    const uint32_t b_base = bs_u + (uint32_t)((lane & 15) * BRPAD + nw * 32 + (lane >> 4) * 8) * 2;

    float o[2][4][2][2][4];   // [mt][nt][r][p][x]  = 128 regs
    #pragma unroll
    for (int i = 0; i < 2; i++)
        #pragma unroll
        for (int j = 0; j < 4; j++)
            #pragma unroll
            for (int r = 0; r < 2; r++)
                #pragma unroll
                for (int p = 0; p < 2; p++)
                    #pragma unroll
                    for (int xq = 0; xq < 4; xq++) o[i][j][r][p][xq] = 0.f;

    float acc[2][4][4];
    #pragma unroll
    for (int i = 0; i < 2; i++)
        #pragma unroll
        for (int j = 0; j < 4; j++)
            #pragma unroll
            for (int q = 0; q < 4; q++) acc[i][j][q] = 0.f;

    // stage s == m-component s
    #define LOADST(s, bufsel)                                                         \
    {                                                                                 \
        const __half* ua = Ub + (size_t)(s) * 16384                                   \
                           + (tid >> 4) * 128 + (tid & 15) * 8;                       \
        uint32_t aoff = (uint32_t)(bufsel) * (ASTG * 2);                              \
        _Pragma("unroll")                                                             \
        for (int i = 0; i < 8; i++)                                                   \
            CP_A16(a_dst0 + aoff + i * (16 * ARPAD * 2), ua + i * (16 * 128));        \
        const __half* sb = Vb + ((size_t)(s) * 128 + (tid >> 3)) * NTILE              \
                           + t0 + (tid & 7) * 8;                                      \
        uint32_t boff = (uint32_t)(bufsel) * (BSTG * 2);                              \
        _Pragma("unroll")                                                             \
        for (int i = 0; i < 4; i++)                                                   \
            CP_A16(b_dst0 + boff + i * (32 * BRPAD * 2), sb + (size_t)(i * 32) * NTILE); \
    }

    #define COMPUTE(bufsel)                                                           \
    {                                                                                 \
        uint32_t ao = (uint32_t)(bufsel) * (ASTG * 2);                                \
        uint32_t bo = (uint32_t)(bufsel) * (BSTG * 2);                                \
        _Pragma("unroll")                                                             \
        for (int kc = 0; kc < 8; kc++) {                                              \
            uint32_t qa0[4], qa1[4], qb0[4], qb1[4];                                  \
            LDM(qa0, a_base + ao + kc * 32);                                          \
            LDM(qa1, a_base + ao + kc * 32 + 16 * ARPAD * 2);                         \
            LDMT(qb0, b_base + bo + kc * (16 * BRPAD * 2));                           \
            LDMT(qb1, b_base + bo + kc * (16 * BRPAD * 2) + 32);                      \
            MMAH(acc[0][0], qa0, qb0[0], qb0[1]);                                     \
            MMAH(acc[1][0], qa1, qb0[0], qb0[1]);                                     \
            MMAH(acc[0][1], qa0, qb0[2], qb0[3]);                                     \
            MMAH(acc[1][1], qa1, qb0[2], qb0[3]);                                     \
            MMAH(acc[0][2], qa0, qb1[0], qb1[1]);                                     \
            MMAH(acc[1][2], qa1, qb1[0], qb1[1]);                                     \
            MMAH(acc[0][3], qa0, qb1[2], qb1[3]);                                     \
            MMAH(acc[1][3], qa1, qb1[2], qb1[3]);                                     \
        }                                                                             \
    }

    LOADST(0, 0);
    CP_COMMIT();

    const float CA0[4] = {1.f, 1.f, 1.f, 0.f};
    const float CA1[4] = {0.f, 1.f, -1.f, -1.f};

    int buf = 0;
    #pragma unroll 1
    for (int m = 0; m < 16; m++) {
        int bufn = (buf == 2) ? 0 : buf + 1;
        if (m < NSTG - 1) {
            LOADST(m + 1, bufn);
            CP_COMMIT();
            CP_WAIT1();
        } else {
            CP_WAIT0();
        }
        __syncthreads();
        COMPUTE(buf);
        buf = bufn;

        // fold component m into output registers
        int u = m >> 2, v = m & 3;
        float cy0 = CA0[u], cy1 = CA1[u];
        float cx0 = CA0[v], cx1 = CA1[v];
        float c00 = cy0 * cx0, c01 = cy0 * cx1, c10 = cy1 * cx0, c11 = cy1 * cx1;
        #pragma unroll
        for (int mt = 0; mt < 2; mt++)
            #pragma unroll
            for (int nt = 0; nt < 4; nt++)
                #pragma unroll
                for (int i = 0; i < 4; i++) {
                    float a = acc[mt][nt][i];
                    int r = i >> 1, tl = i & 1;
                    o[mt][nt][r][0][2 * tl + 0] = fmaf(c00, a, o[mt][nt][r][0][2 * tl + 0]);
                    o[mt][nt][r][0][2 * tl + 1] = fmaf(c01, a, o[mt][nt][r][0][2 * tl + 1]);
                    o[mt][nt][r][1][2 * tl + 0] = fmaf(c10, a, o[mt][nt][r][1][2 * tl + 0]);
                    o[mt][nt][r][1][2 * tl + 1] = fmaf(c11, a, o[mt][nt][r][1][2 * tl + 1]);
                    acc[mt][nt][i] = 0.f;
                }
    }

    // epilogue: (o + bias) * fbm -> out  (tile-row, fully coalesced float4)
    int ty = blockIdx.x;
    #pragma unroll
    for (int mt = 0; mt < 2; mt++)
        #pragma unroll
        for (int r = 0; r < 2; r++) {
            int oc = mb + mt * 16 + g + r * 8;
            float bi = bias[oc];
            float sc = fbm[oc];
            #pragma unroll
            for (int nt = 0; nt < 4; nt++) {
                int xg = 64 * nw + 16 * nt + 4 * tig;
                #pragma unroll
                for (int p = 0; p < 2; p++) {
                    int yg = 2 * ty + p;
                    float4 vv;
                    vv.x = (o[mt][nt][r][p][0] + bi) * sc;
                    vv.y = (o[mt][nt][r][p][1] + bi) * sc;
                    vv.z = (o[mt][nt][r][p][2] + bi) * sc;
                    vv.w = (o[mt][nt][r][p][3] + bi) * sc;
                    *(float4*)(out + (((size_t)(b * NCOUT + oc)) * NHW + yg) * NHW + xg) = vv;
                }
            }
        }
}

// ---------------- launch ----------------
extern "C" void kernel_launch(void* const* d_in, const int* in_sizes, int n_in,
                              void* d_out, int out_size) {
    const float* x    = (const float*)d_in[0];
    const float* dft  = (const float*)d_in[1];
    const float* ksm  = (const float*)d_in[2];
    const float* bias = (const float*)d_in[3];
    const float* fbm  = (const float*)d_in[4];
    float* out = (float*)d_out;

    wino_input_kernel<<<NB * NCIN, 256>>>(x);          // also produces g_pooled
    att_kernel<<<1, 1024>>>(ksm);
    agg_kernel<<<KCOLS / 1024, 256>>>(dft);
    wino_weight_kernel<<<(NB * NCOUT * NCIN) / 256, 256>>>();

    const int dyn = 3 * (ASTG + BSTG) * 2;             // 159,744 bytes
    cudaFuncSetAttribute(wino_gemm_kernel, cudaFuncAttributeMaxDynamicSharedMemorySize, dyn);
    wino_gemm_kernel<<<dim3(NTILE / 64, NB), 256, dyn>>>(bias, fbm, out);
}